// round 3
// baseline (speedup 1.0000x reference)
#include <cuda_runtime.h>
#include <math.h>

// Problem shape constants
#define BB   8
#define HHH  1024
#define WWW  1024
#define TW   128     // tile width  (output pixels)
#define TH   16      // tile height (output pixels)
#define NTHREADS 256

// Accumulator layout (doubles):
//  [0]        focal sum  (Σ over all 3 slices, all pixels, of -log(pt+eps))
//  [1]        edge  sum  (Σ of -log(pt+eps) * |t - ave|)
//  [2  + s*8 + b]  Σ p1          per slice s, batch b
//  [26 + s*8 + b]  Σ p1 * t      per slice s, batch b
//  [50 + b]        Σ t           per batch b
__device__ double g_acc[58];

__global__ void zero_kernel() {
    int i = threadIdx.x;
    if (i < 58) g_acc[i] = 0.0;
}

__global__ __launch_bounds__(NTHREADS)
void main_kernel(const float* __restrict__ pred,
                 const float* __restrict__ diss,
                 const int*   __restrict__ target)
{
    // target tile with halo 3: rows [h0-3, h0+TH+3), cols [w0-3, w0+TW+3)
    __shared__ int   raw[22][136];   // 22 rows x 134 used cols (pad to 136)
    __shared__ int   rs5[20][128];   // 5-wide horizontal sums, rows raw[1..20]
    __shared__ float red[9][8];

    const int b  = blockIdx.z;
    const int w0 = blockIdx.x * TW;
    const int h0 = blockIdx.y * TH;
    const int tx = threadIdx.x;          // 0..31
    const int ty = threadIdx.y;          // 0..7
    const int tid = ty * 32 + tx;

    const int* tgt_b = target + (size_t)b * HHH * WWW;

    // ---- load target tile (zero-padded SAME boundary) ----
    for (int i = tid; i < 22 * 134; i += NTHREADS) {
        int hh = i / 134, cc = i % 134;
        int gh = h0 - 3 + hh, gw = w0 - 3 + cc;
        int v = 0;
        if (gh >= 0 && gh < HHH && gw >= 0 && gw < WWW)
            v = tgt_b[(size_t)gh * WWW + gw];
        raw[hh][cc] = v;
    }
    __syncthreads();

    // ---- stage 1: horizontal 5-sums (center raw col = w+3, raw row = r+1) ----
    for (int i = tid; i < 20 * 128; i += NTHREADS) {
        int r = i >> 7, w = i & 127;
        rs5[r][w] = raw[r+1][w+1] + raw[r+1][w+2] + raw[r+1][w+3]
                  + raw[r+1][w+4] + raw[r+1][w+5];
    }
    __syncthreads();

    float facc = 0.f, eacc = 0.f;
    float p1s0 = 0.f, p1s1 = 0.f, p1s2 = 0.f;
    float p1t0 = 0.f, p1t1 = 0.f, p1t2 = 0.f;
    float tcf  = 0.f;

    const size_t hw = (size_t)HHH * WWW;

    #pragma unroll
    for (int rr = 0; rr < 2; rr++) {
        const int oh = ty * 2 + rr;            // 0..15 within tile
        const int gh = h0 + oh;
        const int gwb = w0 + tx * 4;
        const size_t pix = (size_t)gh * WWW + gwb;

        // slice 0 (pred i=0), slice 1 (pred i=1), slice 2 (Diss j=0)
        float4 a0 = *(const float4*)(pred + ((size_t)( b     )*2 + 0) * hw + pix);
        float4 a1 = *(const float4*)(pred + ((size_t)( b     )*2 + 1) * hw + pix);
        float4 q0 = *(const float4*)(pred + ((size_t)( 8 + b )*2 + 0) * hw + pix);
        float4 q1 = *(const float4*)(pred + ((size_t)( 8 + b )*2 + 1) * hw + pix);
        float4 c0 = *(const float4*)(diss + ((size_t)( b     )*2 + 0) * hw + pix);
        float4 c1 = *(const float4*)(diss + ((size_t)( b     )*2 + 1) * hw + pix);

        const float* a0f = (const float*)&a0;
        const float* a1f = (const float*)&a1;
        const float* q0f = (const float*)&q0;
        const float* q1f = (const float*)&q1;
        const float* c0f = (const float*)&c0;
        const float* c1f = (const float*)&c1;

        const int hr = oh + 3;

        #pragma unroll
        for (int j = 0; j < 4; j++) {
            const int wcol = tx * 4 + j;   // output col within tile, 0..127
            const int wr   = wcol + 3;     // raw col of center

            const int t = raw[hr][wr];
            // 29-cell circular mask = 5x5 box + (±3,0) + (0,±3)
            int s29 = rs5[oh  ][wcol] + rs5[oh+1][wcol] + rs5[oh+2][wcol]
                    + rs5[oh+3][wcol] + rs5[oh+4][wcol]
                    + raw[hr][wcol] + raw[hr][wcol+6]    // (0,-3),(0,+3)
                    + raw[oh][wr]   + raw[oh+6][wr];     // (-3,0),(+3,0)

            const float tf = (float)t;
            const float at = fabsf(tf - (float)s29 * (1.0f / 29.0f));

            // slice 0 : softmax over 2 channels
            {
                float d  = a0f[j] - a1f[j];
                float e  = __expf(d);
                float p1 = 1.0f / (1.0f + e);
                float p0 = e * p1;
                float pt = t ? p1 : p0;
                float lp = __logf(pt + 1e-10f);
                facc -= lp; eacc -= lp * at;
                p1s0 += p1; p1t0 += p1 * tf;
            }
            // slice 1 : softmax over 2 channels
            {
                float d  = q0f[j] - q1f[j];
                float e  = __expf(d);
                float p1 = 1.0f / (1.0f + e);
                float p0 = e * p1;
                float pt = t ? p1 : p0;
                float lp = __logf(pt + 1e-10f);
                facc -= lp; eacc -= lp * at;
                p1s1 += p1; p1t1 += p1 * tf;
            }
            // slice 2 : raw Diss probabilities (no softmax in reference)
            {
                float p0 = c0f[j];
                float p1 = c1f[j];
                float pt = t ? p1 : p0;
                float lp = __logf(pt + 1e-10f);
                facc -= lp; eacc -= lp * at;
                p1s2 += p1; p1t2 += p1 * tf;
            }
            tcf += tf;
        }
    }

    // ---- block reduction: warp shuffles, then 8 warp partials per value ----
    float vals[9] = {facc, eacc, p1s0, p1s1, p1s2, p1t0, p1t1, p1t2, tcf};
    #pragma unroll
    for (int k = 0; k < 9; k++) {
        float v = vals[k];
        #pragma unroll
        for (int o = 16; o; o >>= 1) v += __shfl_xor_sync(0xFFFFFFFFu, v, o);
        if ((tid & 31) == 0) red[k][tid >> 5] = v;
    }
    __syncthreads();

    if (tid < 9) {
        float s = 0.f;
        #pragma unroll
        for (int w = 0; w < 8; w++) s += red[tid][w];
        int addr;
        if      (tid == 0) addr = 0;
        else if (tid == 1) addr = 1;
        else if (tid <  5) addr = 2  + (tid - 2) * 8 + b;
        else if (tid <  8) addr = 26 + (tid - 5) * 8 + b;
        else               addr = 50 + b;
        atomicAdd(&g_acc[addr], (double)s);
    }
}

__global__ void finalize_kernel(const float* __restrict__ diff,
                                const float* __restrict__ sigma,
                                float* __restrict__ out)
{
    // sigmas = sigma * sigma (match reference f32 squaring)
    float sf0 = sigma[0] * sigma[0];
    float sf1 = sigma[1] * sigma[1];
    float sf2 = sigma[2] * sigma[2];
    double s0 = (double)sf0, s1 = (double)sf1, s2 = (double)sf2;

    const double Np = 8.0 * 1024.0 * 1024.0;   // B*H*W per slice

    double focal = g_acc[0] / Np / s0;
    double edge  = g_acc[1] / Np / s2;

    double dice = 0.0;
    for (int s = 0; s < 3; s++) {
        double m = 0.0;
        for (int bb = 0; bb < 8; bb++) {
            double I = g_acc[26 + s * 8 + bb];
            double U = g_acc[2  + s * 8 + bb] + g_acc[50 + bb];
            m += 2.0 * I / (U + 1e-10);
        }
        dice += 1.0 - m / 8.0;
    }

    double loss = focal + dice / s1 + edge
                + (double)diff[0]
                + 0.5 * (log(s0) + log(s1) + log(s2));
    out[0] = (float)loss;
}

extern "C" void kernel_launch(void* const* d_in, const int* in_sizes, int n_in,
                              void* d_out, int out_size)
{
    const float* pred   = (const float*)d_in[0];  // (2,8,2,1024,1024) f32
    const float* diss   = (const float*)d_in[1];  // (1,8,2,1024,1024) f32
    const int*   target = (const int*)  d_in[2];  // (8,1024,1024) i32
    const float* diff   = (const float*)d_in[3];  // scalar f32
    const float* sigma  = (const float*)d_in[4];  // (3,) f32
    float* out = (float*)d_out;

    zero_kernel<<<1, 64>>>();
    dim3 grid(WWW / TW, HHH / TH, BB);   // (8, 64, 8)
    dim3 block(32, 8);
    main_kernel<<<grid, block>>>(pred, diss, target);
    finalize_kernel<<<1, 1>>>(diff, sigma, out);
}

// round 6
// speedup vs baseline: 1.3700x; 1.3700x over previous
#include <cuda_runtime.h>
#include <math.h>

// Problem shape constants
#define BB   8
#define HHH  1024
#define WWW  1024
#define TW   128     // tile width  (output pixels)
#define TH   16      // tile height (output pixels)
#define NTHREADS 256

// Accumulator layout (doubles):
//  [0]        focal sum  (Σ over all 3 slices, all pixels, of -log(pt+eps))
//  [1]        edge  sum  (Σ of -log(pt+eps) * |t - ave|)
//  [2  + s*8 + b]  Σ p1          per slice s, batch b
//  [26 + s*8 + b]  Σ p1 * t      per slice s, batch b
//  [50 + b]        Σ t           per batch b
// Zero-initialized at module load; finalize_kernel re-zeroes after reading,
// so every graph replay starts from a clean state.
__device__ double g_acc[58];

__global__ __launch_bounds__(NTHREADS)
void main_kernel(const float* __restrict__ pred,
                 const float* __restrict__ diss,
                 const int*   __restrict__ target)
{
    // target tile (as float) with halo 3: rows [h0-3, h0+TH+3), cols [w0-3, w0+TW+3)
    __shared__ float raw[22][136];   // 22 rows x 134 used cols (pad to 136)
    __shared__ float rs5[20][128];   // 5-wide horizontal sums, rows raw[1..20]
    __shared__ float red[9][8];

    const int b  = blockIdx.z;
    const int w0 = blockIdx.x * TW;
    const int h0 = blockIdx.y * TH;
    const int tx = threadIdx.x;          // 0..31
    const int ty = threadIdx.y;          // 0..7
    const int tid = ty * 32 + tx;

    const int* tgt_b = target + (size_t)b * HHH * WWW;

    // ---- load target tile (zero-padded SAME boundary), convert to float once ----
    for (int i = tid; i < 22 * 134; i += NTHREADS) {
        int hh = i / 134, cc = i - hh * 134;
        int gh = h0 - 3 + hh, gw = w0 - 3 + cc;
        float v = 0.f;
        if (gh >= 0 && gh < HHH && gw >= 0 && gw < WWW)
            v = (float)tgt_b[(size_t)gh * WWW + gw];
        raw[hh][cc] = v;
    }
    __syncthreads();

    // ---- stage 1: horizontal 5-sums (center raw col = w+3, raw row = r+1) ----
    // linear mapping: lanes hit consecutive columns -> conflict-free
    for (int i = tid; i < 20 * 128; i += NTHREADS) {
        int r = i >> 7, w = i & 127;
        rs5[r][w] = raw[r+1][w+1] + raw[r+1][w+2] + raw[r+1][w+3]
                  + raw[r+1][w+4] + raw[r+1][w+5];
    }
    __syncthreads();

    float facc = 0.f, eacc = 0.f;
    float p1s0 = 0.f, p1s1 = 0.f, p1s2 = 0.f;
    float p1t0 = 0.f, p1t1 = 0.f, p1t2 = 0.f;
    float tcf  = 0.f;

    const size_t hw = (size_t)HHH * WWW;
    const float* pl_a0 = pred + ((size_t)b        * 2 + 0) * hw;
    const float* pl_a1 = pred + ((size_t)b        * 2 + 1) * hw;
    const float* pl_q0 = pred + ((size_t)(8 + b)  * 2 + 0) * hw;
    const float* pl_q1 = pred + ((size_t)(8 + b)  * 2 + 1) * hw;
    const float* pl_c0 = diss + ((size_t)b        * 2 + 0) * hw;
    const float* pl_c1 = diss + ((size_t)b        * 2 + 1) * hw;

    #pragma unroll
    for (int rr = 0; rr < 2; rr++) {
        const int oh = ty * 2 + rr;            // 0..15 within tile
        const size_t base = (size_t)(h0 + oh) * WWW + w0 + tx;
        const int hr = oh + 3;

        // Front-batch all 24 scalar loads (coalesced 128B/warp-instr, high MLP)
        float a0[4], a1[4], q0[4], q1[4], c0[4], c1[4];
        #pragma unroll
        for (int j = 0; j < 4; j++) {
            size_t p = base + 32 * j;
            a0[j] = __ldcs(pl_a0 + p);  a1[j] = __ldcs(pl_a1 + p);
            q0[j] = __ldcs(pl_q0 + p);  q1[j] = __ldcs(pl_q1 + p);
            c0[j] = __ldcs(pl_c0 + p);  c1[j] = __ldcs(pl_c1 + p);
        }

        #pragma unroll
        for (int j = 0; j < 4; j++) {
            const int c  = tx + 32 * j;    // output col within tile (lane-consecutive!)
            const int wr = c + 3;          // raw col of center

            const float tf = raw[hr][wr];
            // 29-cell circular mask = 5x5 box + (±3,0) + (0,±3)
            float s29 = rs5[oh  ][c] + rs5[oh+1][c] + rs5[oh+2][c]
                      + rs5[oh+3][c] + rs5[oh+4][c]
                      + raw[hr][c] + raw[hr][c+6]    // (0,-3),(0,+3)
                      + raw[oh][wr] + raw[oh+6][wr]; // (-3,0),(+3,0)

            const float at = fabsf(tf - s29 * (1.0f / 29.0f));
            const bool  t1 = tf > 0.5f;

            // slice 0 : softmax over 2 channels.
            // p1 = 1/(1+e^d), p0 = e^d/(1+e^d); since |d| <~ 9, p >> eps, so
            // -log(pt+eps) == t ? L : L-d with L = log(1+e^d) (to ~2e-6 abs).
            {
                float d  = a0[j] - a1[j];
                float e  = __expf(d);
                float z  = 1.0f + e;
                float L  = __logf(z);
                float p1 = __fdividef(1.0f, z);
                float nl = t1 ? L : (L - d);
                facc += nl; eacc += nl * at;
                p1s0 += p1; p1t0 += t1 ? p1 : 0.0f;
            }
            // slice 1 : softmax over 2 channels
            {
                float d  = q0[j] - q1[j];
                float e  = __expf(d);
                float z  = 1.0f + e;
                float L  = __logf(z);
                float p1 = __fdividef(1.0f, z);
                float nl = t1 ? L : (L - d);
                facc += nl; eacc += nl * at;
                p1s1 += p1; p1t1 += t1 ? p1 : 0.0f;
            }
            // slice 2 : raw Diss probabilities (can be ~0 -> keep eps)
            {
                float p0 = c0[j];
                float p1 = c1[j];
                float pt = t1 ? p1 : p0;
                float nl = -__logf(pt + 1e-10f);
                facc += nl; eacc += nl * at;
                p1s2 += p1; p1t2 += t1 ? p1 : 0.0f;
            }
            tcf += tf;
        }
    }

    // ---- block reduction: warp shuffles, then 8 warp partials per value ----
    float vals[9] = {facc, eacc, p1s0, p1s1, p1s2, p1t0, p1t1, p1t2, tcf};
    #pragma unroll
    for (int k = 0; k < 9; k++) {
        float v = vals[k];
        #pragma unroll
        for (int o = 16; o; o >>= 1) v += __shfl_xor_sync(0xFFFFFFFFu, v, o);
        if ((tid & 31) == 0) red[k][tid >> 5] = v;
    }
    __syncthreads();

    if (tid < 9) {
        float s = 0.f;
        #pragma unroll
        for (int w = 0; w < 8; w++) s += red[tid][w];
        int addr;
        if      (tid == 0) addr = 0;
        else if (tid == 1) addr = 1;
        else if (tid <  5) addr = 2  + (tid - 2) * 8 + b;
        else if (tid <  8) addr = 26 + (tid - 5) * 8 + b;
        else               addr = 50 + b;
        atomicAdd(&g_acc[addr], (double)s);
    }
}

__global__ void finalize_kernel(const float* __restrict__ diff,
                                const float* __restrict__ sigma,
                                float* __restrict__ out)
{
    // sigmas = sigma * sigma (match reference f32 squaring)
    float sf0 = sigma[0] * sigma[0];
    float sf1 = sigma[1] * sigma[1];
    float sf2 = sigma[2] * sigma[2];
    double s0 = (double)sf0, s1 = (double)sf1, s2 = (double)sf2;

    const double Np = 8.0 * 1024.0 * 1024.0;   // B*H*W per slice

    double focal = g_acc[0] / Np / s0;
    double edge  = g_acc[1] / Np / s2;

    double dice = 0.0;
    for (int s = 0; s < 3; s++) {
        double m = 0.0;
        for (int bb = 0; bb < 8; bb++) {
            double I = g_acc[26 + s * 8 + bb];
            double U = g_acc[2  + s * 8 + bb] + g_acc[50 + bb];
            m += 2.0 * I / (U + 1e-10);
        }
        dice += 1.0 - m / 8.0;
    }

    double loss = focal + dice / s1 + edge
                + (double)diff[0]
                + 0.5 * (log(s0) + log(s1) + log(s2));
    out[0] = (float)loss;

    // Re-zero accumulators for the next graph replay (single thread: reads
    // above are complete before these writes).
    for (int i = 0; i < 58; i++) g_acc[i] = 0.0;
}

extern "C" void kernel_launch(void* const* d_in, const int* in_sizes, int n_in,
                              void* d_out, int out_size)
{
    const float* pred   = (const float*)d_in[0];  // (2,8,2,1024,1024) f32
    const float* diss   = (const float*)d_in[1];  // (1,8,2,1024,1024) f32
    const int*   target = (const int*)  d_in[2];  // (8,1024,1024) i32
    const float* diff   = (const float*)d_in[3];  // scalar f32
    const float* sigma  = (const float*)d_in[4];  // (3,) f32
    float* out = (float*)d_out;

    dim3 grid(WWW / TW, HHH / TH, BB);   // (8, 64, 8)
    dim3 block(32, 8);
    main_kernel<<<grid, block>>>(pred, diss, target);
    finalize_kernel<<<1, 1>>>(diff, sigma, out);
}

// round 7
// speedup vs baseline: 1.5885x; 1.1595x over previous
#include <cuda_runtime.h>
#include <math.h>

// Problem shape constants
#define BB   8
#define HHH  1024
#define WWW  1024
#define TW   128     // tile width  (output pixels)
#define TH   16      // tile height (output pixels)
#define NTHREADS 256

// Accumulator layout (doubles):
//  [0]        focal sum  (Σ over all 3 slices, all pixels, of -log(pt+eps))
//  [1]        edge  sum  (Σ of -log(pt+eps) * |t - ave|)
//  [2  + s*8 + b]  Σ p1          per slice s, batch b
//  [26 + s*8 + b]  Σ p1 * t      per slice s, batch b
//  [50 + b]        Σ t           per batch b
// Zero-initialized at module load; finalize_kernel re-zeroes after reading,
// so every graph replay starts from a clean state.
__device__ double g_acc[58];

__global__ __launch_bounds__(NTHREADS)
void main_kernel(const float* __restrict__ pred,
                 const float* __restrict__ diss,
                 const int*   __restrict__ target)
{
    // target tile (as float) with halo 3: rows [h0-3, h0+TH+3), cols [w0-3, w0+TW+3)
    __shared__ float raw[22][136];   // 22 rows x 134 used cols (pad to 136)
    __shared__ float rs5[20][128];   // 5-wide horizontal sums, rows raw[1..20]
    __shared__ float red[9][8];

    const int b  = blockIdx.z;
    const int w0 = blockIdx.x * TW;
    const int h0 = blockIdx.y * TH;
    const int tx = threadIdx.x;          // 0..31
    const int ty = threadIdx.y;          // 0..7
    const int tid = ty * 32 + tx;

    const int* tgt_b = target + (size_t)b * HHH * WWW;

    // ---- load target tile (zero-padded SAME boundary), convert to float once ----
    for (int i = tid; i < 22 * 134; i += NTHREADS) {
        int hh = i / 134, cc = i - hh * 134;
        int gh = h0 - 3 + hh, gw = w0 - 3 + cc;
        float v = 0.f;
        if (gh >= 0 && gh < HHH && gw >= 0 && gw < WWW)
            v = (float)tgt_b[(size_t)gh * WWW + gw];
        raw[hh][cc] = v;
    }
    __syncthreads();

    // ---- stage 1: horizontal 5-sums (center raw col = w+3, raw row = r+1) ----
    // linear mapping: lanes hit consecutive columns -> conflict-free
    for (int i = tid; i < 20 * 128; i += NTHREADS) {
        int r = i >> 7, w = i & 127;
        rs5[r][w] = raw[r+1][w+1] + raw[r+1][w+2] + raw[r+1][w+3]
                  + raw[r+1][w+4] + raw[r+1][w+5];
    }
    __syncthreads();

    float facc = 0.f, eacc = 0.f;
    float p1s0 = 0.f, p1s1 = 0.f, p1s2 = 0.f;
    float p1t0 = 0.f, p1t1 = 0.f, p1t2 = 0.f;
    float tcf  = 0.f;

    const size_t hw = (size_t)HHH * WWW;
    const float* pl_a0 = pred + ((size_t)b        * 2 + 0) * hw;
    const float* pl_a1 = pred + ((size_t)b        * 2 + 1) * hw;
    const float* pl_q0 = pred + ((size_t)(8 + b)  * 2 + 0) * hw;
    const float* pl_q1 = pred + ((size_t)(8 + b)  * 2 + 1) * hw;
    const float* pl_c0 = diss + ((size_t)b        * 2 + 0) * hw;
    const float* pl_c1 = diss + ((size_t)b        * 2 + 1) * hw;

    #pragma unroll
    for (int rr = 0; rr < 2; rr++) {
        const int oh = ty * 2 + rr;            // 0..15 within tile
        const size_t base = (size_t)(h0 + oh) * WWW + w0 + tx;
        const int hr = oh + 3;

        // Front-batch all 24 scalar loads (coalesced 128B/warp-instr, high MLP)
        float a0[4], a1[4], q0[4], q1[4], c0[4], c1[4];
        #pragma unroll
        for (int j = 0; j < 4; j++) {
            size_t p = base + 32 * j;
            a0[j] = __ldcs(pl_a0 + p);  a1[j] = __ldcs(pl_a1 + p);
            q0[j] = __ldcs(pl_q0 + p);  q1[j] = __ldcs(pl_q1 + p);
            c0[j] = __ldcs(pl_c0 + p);  c1[j] = __ldcs(pl_c1 + p);
        }

        #pragma unroll
        for (int j = 0; j < 4; j++) {
            const int c  = tx + 32 * j;    // output col within tile (lane-consecutive!)
            const int wr = c + 3;          // raw col of center

            const float tf = raw[hr][wr];
            // 29-cell circular mask = 5x5 box + (±3,0) + (0,±3)
            float s29 = rs5[oh  ][c] + rs5[oh+1][c] + rs5[oh+2][c]
                      + rs5[oh+3][c] + rs5[oh+4][c]
                      + raw[hr][c] + raw[hr][c+6]    // (0,-3),(0,+3)
                      + raw[oh][wr] + raw[oh+6][wr]; // (-3,0),(+3,0)

            const float at = fabsf(tf - s29 * (1.0f / 29.0f));
            const bool  t1 = tf > 0.5f;

            // slice 0 : softmax over 2 channels.
            // p1 = 1/(1+e^d), p0 = e^d/(1+e^d); since |d| <~ 9, p >> eps, so
            // -log(pt+eps) == t ? L : L-d with L = log(1+e^d) (to ~2e-6 abs).
            {
                float d  = a0[j] - a1[j];
                float e  = __expf(d);
                float z  = 1.0f + e;
                float L  = __logf(z);
                float p1 = __fdividef(1.0f, z);
                float nl = t1 ? L : (L - d);
                facc += nl; eacc += nl * at;
                p1s0 += p1; p1t0 += t1 ? p1 : 0.0f;
            }
            // slice 1 : softmax over 2 channels
            {
                float d  = q0[j] - q1[j];
                float e  = __expf(d);
                float z  = 1.0f + e;
                float L  = __logf(z);
                float p1 = __fdividef(1.0f, z);
                float nl = t1 ? L : (L - d);
                facc += nl; eacc += nl * at;
                p1s1 += p1; p1t1 += t1 ? p1 : 0.0f;
            }
            // slice 2 : raw Diss probabilities (can be ~0 -> keep eps)
            {
                float p0 = c0[j];
                float p1 = c1[j];
                float pt = t1 ? p1 : p0;
                float nl = -__logf(pt + 1e-10f);
                facc += nl; eacc += nl * at;
                p1s2 += p1; p1t2 += t1 ? p1 : 0.0f;
            }
            tcf += tf;
        }
    }

    // ---- block reduction: warp shuffles, then 8 warp partials per value ----
    float vals[9] = {facc, eacc, p1s0, p1s1, p1s2, p1t0, p1t1, p1t2, tcf};
    #pragma unroll
    for (int k = 0; k < 9; k++) {
        float v = vals[k];
        #pragma unroll
        for (int o = 16; o; o >>= 1) v += __shfl_xor_sync(0xFFFFFFFFu, v, o);
        if ((tid & 31) == 0) red[k][tid >> 5] = v;
    }
    __syncthreads();

    if (tid < 9) {
        float s = 0.f;
        #pragma unroll
        for (int w = 0; w < 8; w++) s += red[tid][w];
        int addr;
        if      (tid == 0) addr = 0;
        else if (tid == 1) addr = 1;
        else if (tid <  5) addr = 2  + (tid - 2) * 8 + b;
        else if (tid <  8) addr = 26 + (tid - 5) * 8 + b;
        else               addr = 50 + b;
        atomicAdd(&g_acc[addr], (double)s);
    }
}

// One-warp finalize: all g_acc loads issue in parallel (one latency wave),
// dice terms reduced via shuffles. Lane 0 writes the scalar result.
__global__ __launch_bounds__(32)
void finalize_kernel(const float* __restrict__ diff,
                     const float* __restrict__ sigma,
                     float* __restrict__ out)
{
    const int lane = threadIdx.x;

    // ---- parallel loads (independent; high MLP) ----
    // Dice term for (s,b) pair on lanes 0..23:
    double term = 0.0;
    if (lane < 24) {
        int s = lane >> 3, bb = lane & 7;
        double I = g_acc[26 + s * 8 + bb];
        double U = g_acc[2  + s * 8 + bb] + g_acc[50 + bb];
        term = 2.0 * I / (U + 1e-10);
    }
    double fsum = g_acc[0];   // every lane loads (broadcast via L2); cheap
    double esum = g_acc[1];

    // ---- warp reduction of dice terms (double via two 32-bit shuffles) ----
    #pragma unroll
    for (int o = 16; o; o >>= 1)
        term += __shfl_xor_sync(0xFFFFFFFFu, term, o);
    // dice = sum over s of (1 - mean_b(term)) = 3 - term_total / 8
    double dice = 3.0 - term / 8.0;

    if (lane == 0) {
        float sf0 = sigma[0] * sigma[0];
        float sf1 = sigma[1] * sigma[1];
        float sf2 = sigma[2] * sigma[2];
        double s0 = (double)sf0, s1 = (double)sf1, s2 = (double)sf2;

        const double Np = 8.0 * 1024.0 * 1024.0;   // B*H*W per slice

        double loss = fsum / Np / s0
                    + dice / s1
                    + esum / Np / s2
                    + (double)diff[0]
                    + 0.5 * (log(s0) + log(s1) + log(s2));
        out[0] = (float)loss;
    }

    // ---- re-zero accumulators for next replay (all reads above are done:
    // every g_acc element was consumed before this point in-warp, and the
    // shuffle reduction synchronized the warp) ----
    __syncwarp();
    if (lane < 29) { g_acc[lane] = 0.0; g_acc[lane + 29] = 0.0; }
}

extern "C" void kernel_launch(void* const* d_in, const int* in_sizes, int n_in,
                              void* d_out, int out_size)
{
    const float* pred   = (const float*)d_in[0];  // (2,8,2,1024,1024) f32
    const float* diss   = (const float*)d_in[1];  // (1,8,2,1024,1024) f32
    const int*   target = (const int*)  d_in[2];  // (8,1024,1024) i32
    const float* diff   = (const float*)d_in[3];  // scalar f32
    const float* sigma  = (const float*)d_in[4];  // (3,) f32
    float* out = (float*)d_out;

    dim3 grid(WWW / TW, HHH / TH, BB);   // (8, 64, 8)
    dim3 block(32, 8);
    main_kernel<<<grid, block>>>(pred, diss, target);
    finalize_kernel<<<1, 32>>>(diff, sigma, out);
}